// round 1
// baseline (speedup 1.0000x reference)
#include <cuda_runtime.h>
#include <math.h>
#include <stdint.h>

#define T_TOK 2048
#define H_DIM 1024
#define F_DIM 4096
#define E_NUM 8

// Scratch (static device globals: allocation-free per harness rules)
__device__ float g_act[(4096 + 256) * F_DIM];   // padded rows: off+m can exceed 4096 by <128+... (bounded 4222)
__device__ int   g_list[E_NUM * T_TOK];
__device__ float g_wgt [E_NUM * T_TOK];
__device__ int   g_cnt[E_NUM];
__device__ int   g_off[E_NUM];
__device__ int   g_tidx[T_TOK * 2];
__device__ float g_tw  [T_TOK * 2];

__device__ __forceinline__ float to_tf32(float x) {
    unsigned u;
    asm("cvt.rna.tf32.f32 %0, %1;" : "=r"(u) : "f"(x));
    return __uint_as_float(u);
}

__device__ __forceinline__ void mma_tf32(float* c, const float* a, const float* b) {
    const unsigned* A = reinterpret_cast<const unsigned*>(a);
    const unsigned* B = reinterpret_cast<const unsigned*>(b);
    asm volatile(
        "mma.sync.aligned.m16n8k8.row.col.f32.tf32.tf32.f32 "
        "{%0,%1,%2,%3}, {%4,%5,%6,%7}, {%8,%9}, {%0,%1,%2,%3};\n"
        : "+f"(c[0]), "+f"(c[1]), "+f"(c[2]), "+f"(c[3])
        : "r"(A[0]), "r"(A[1]), "r"(A[2]), "r"(A[3]), "r"(B[0]), "r"(B[1]));
}

__device__ __forceinline__ float gelu_exact(float v) {
    return 0.5f * v * (1.0f + erff(v * 0.70710678118654752440f));
}

// ---------------------------------------------------------------- zero output
__global__ void zero_kernel(float4* out) {
    out[blockIdx.x * blockDim.x + threadIdx.x] = make_float4(0.f, 0.f, 0.f, 0.f);
}

// ---------------------------------------------------------------- router
__global__ void router_kernel(const float* __restrict__ x, const float* __restrict__ gw) {
    int warp = (blockIdx.x * blockDim.x + threadIdx.x) >> 5;
    int lane = threadIdx.x & 31;
    if (warp >= T_TOK) return;
    float acc[E_NUM];
#pragma unroll
    for (int e = 0; e < E_NUM; e++) acc[e] = 0.f;
    const float* xr = x + (size_t)warp * H_DIM;
    for (int h = lane; h < H_DIM; h += 32) {
        float xv = xr[h];
#pragma unroll
        for (int e = 0; e < E_NUM; e++) acc[e] += xv * gw[e * H_DIM + h];
    }
#pragma unroll
    for (int e = 0; e < E_NUM; e++) {
#pragma unroll
        for (int o = 16; o > 0; o >>= 1) acc[e] += __shfl_xor_sync(0xffffffffu, acc[e], o);
    }
    if (lane == 0) {
        float p[E_NUM], mx = -1e30f;
#pragma unroll
        for (int e = 0; e < E_NUM; e++) {
            p[e] = 30.0f * tanhf(acc[e] * (1.0f / 30.0f));
            mx = fmaxf(mx, p[e]);
        }
        float s = 0.f;
#pragma unroll
        for (int e = 0; e < E_NUM; e++) { p[e] = expf(p[e] - mx); s += p[e]; }
        int i0 = 0;
#pragma unroll
        for (int e = 1; e < E_NUM; e++) if (p[e] > p[i0]) i0 = e;
        int i1 = (i0 == 0) ? 1 : 0;
#pragma unroll
        for (int e = 0; e < E_NUM; e++) if (e != i0 && p[e] > p[i1]) i1 = e;
        float inv = 1.0f / s;
        g_tidx[warp * 2 + 0] = i0;  g_tw[warp * 2 + 0] = p[i0] * inv;
        g_tidx[warp * 2 + 1] = i1;  g_tw[warp * 2 + 1] = p[i1] * inv;
    }
}

// ---------------------------------------------------------------- build per-expert lists
__global__ void build_kernel() {
    int e    = threadIdx.x >> 5;   // 8 warps, one expert each
    int lane = threadIdx.x & 31;
    int cnt  = 0;
    for (int base = 0; base < T_TOK; base += 32) {
        int t = base + lane;
        int i0 = g_tidx[t * 2], i1 = g_tidx[t * 2 + 1];
        bool hit = (i0 == e) || (i1 == e);
        float w = (i0 == e) ? g_tw[t * 2] : g_tw[t * 2 + 1];
        unsigned mask = __ballot_sync(0xffffffffu, hit);
        if (hit) {
            int pos = cnt + __popc(mask & ((1u << lane) - 1u));
            g_list[e * T_TOK + pos] = t;
            g_wgt [e * T_TOK + pos] = w;
        }
        cnt += __popc(mask);
    }
    if (lane == 0) g_cnt[e] = cnt;
    __syncthreads();
    if (threadIdx.x == 0) {
        int off = 0;
        for (int ee = 0; ee < E_NUM; ee++) { g_off[ee] = off; off += g_cnt[ee]; }
    }
}

// ---------------------------------------------------------------- GEMM1: act = w * gelu(X W1^T) * (X W3^T)
// Block tile: M=128, N=64, K=32; 8 warps as 4x2, warp tile 32x32.
__global__ __launch_bounds__(256, 1) void mlp1_kernel(
        const float* __restrict__ x,
        const float* __restrict__ w1,
        const float* __restrict__ w3) {
    __shared__ float As[128][36];
    __shared__ float B1[64][36];
    __shared__ float B3[64][36];
    __shared__ int   ls[128];
    __shared__ float ws[128];

    int e   = blockIdx.z;
    int cnt = g_cnt[e];
    int m0  = blockIdx.y * 128;
    if (m0 >= cnt) return;
    int f0  = blockIdx.x * 64;
    int off = g_off[e];

    int tid = threadIdx.x, lane = tid & 31, wid = tid >> 5;
    int wm = wid >> 1, wn = wid & 1;

    if (tid < 128) {
        int gm = m0 + tid;
        ls[tid] = (gm < cnt) ? g_list[e * T_TOK + gm] : 0;
        ws[tid] = (gm < cnt) ? g_wgt [e * T_TOK + gm] : 0.f;
    }
    __syncthreads();

    float accG[2][4][4], accU[2][4][4];
#pragma unroll
    for (int i = 0; i < 2; i++)
#pragma unroll
        for (int j = 0; j < 4; j++)
#pragma unroll
            for (int k = 0; k < 4; k++) { accG[i][j][k] = 0.f; accU[i][j][k] = 0.f; }

    const float* w1e = w1 + ((size_t)e * F_DIM + f0) * H_DIM;
    const float* w3e = w3 + ((size_t)e * F_DIM + f0) * H_DIM;

    for (int k0 = 0; k0 < H_DIM; k0 += 32) {
        // stage A (gathered rows)
#pragma unroll
        for (int t = 0; t < 4; t++) {
            int idx = tid + t * 256;
            int r = idx >> 3, c4 = (idx & 7) * 4;
            float4 v = *reinterpret_cast<const float4*>(x + (size_t)ls[r] * H_DIM + k0 + c4);
            float4 o = make_float4(to_tf32(v.x), to_tf32(v.y), to_tf32(v.z), to_tf32(v.w));
            *reinterpret_cast<float4*>(&As[r][c4]) = o;
        }
        // stage B1, B3
#pragma unroll
        for (int t = 0; t < 2; t++) {
            int idx = tid + t * 256;
            int r = idx >> 3, c4 = (idx & 7) * 4;
            float4 v = *reinterpret_cast<const float4*>(w1e + (size_t)r * H_DIM + k0 + c4);
            *reinterpret_cast<float4*>(&B1[r][c4]) =
                make_float4(to_tf32(v.x), to_tf32(v.y), to_tf32(v.z), to_tf32(v.w));
            float4 u = *reinterpret_cast<const float4*>(w3e + (size_t)r * H_DIM + k0 + c4);
            *reinterpret_cast<float4*>(&B3[r][c4]) =
                make_float4(to_tf32(u.x), to_tf32(u.y), to_tf32(u.z), to_tf32(u.w));
        }
        __syncthreads();
#pragma unroll
        for (int ks = 0; ks < 4; ks++) {
            int kk = ks * 8;
            float a[2][4];
#pragma unroll
            for (int mt = 0; mt < 2; mt++) {
                int r = wm * 32 + mt * 16 + (lane >> 2);
                int c = kk + (lane & 3);
                a[mt][0] = As[r][c];     a[mt][1] = As[r + 8][c];
                a[mt][2] = As[r][c + 4]; a[mt][3] = As[r + 8][c + 4];
            }
#pragma unroll
            for (int nt = 0; nt < 4; nt++) {
                int col = wn * 32 + nt * 8 + (lane >> 2);
                int c = kk + (lane & 3);
                float b1[2] = { B1[col][c], B1[col][c + 4] };
                float b3[2] = { B3[col][c], B3[col][c + 4] };
#pragma unroll
                for (int mt = 0; mt < 2; mt++) {
                    mma_tf32(accG[mt][nt], a[mt], b1);
                    mma_tf32(accU[mt][nt], a[mt], b3);
                }
            }
        }
        __syncthreads();
    }

    // epilogue: act = weight * gelu(g) * u
#pragma unroll
    for (int mt = 0; mt < 2; mt++) {
        int rbase = wm * 32 + mt * 16 + (lane >> 2);
#pragma unroll
        for (int half = 0; half < 2; half++) {
            int m = rbase + half * 8;
            if (m0 + m >= cnt) continue;
            float wgt = ws[m];
            size_t rowoff = (size_t)(off + m0 + m) * F_DIM;
#pragma unroll
            for (int nt = 0; nt < 4; nt++) {
                int col = f0 + wn * 32 + nt * 8 + (lane & 3) * 2;
                float gg0 = accG[mt][nt][half * 2 + 0];
                float gg1 = accG[mt][nt][half * 2 + 1];
                float uu0 = accU[mt][nt][half * 2 + 0];
                float uu1 = accU[mt][nt][half * 2 + 1];
                float2 o;
                o.x = wgt * uu0 * gelu_exact(gg0);
                o.y = wgt * uu1 * gelu_exact(gg1);
                *reinterpret_cast<float2*>(&g_act[rowoff + col]) = o;
            }
        }
    }
}

// ---------------------------------------------------------------- GEMM2: out += act @ W2^T
__global__ __launch_bounds__(256, 1) void mlp2_kernel(
        const float* __restrict__ w2, float* __restrict__ out) {
    __shared__ float As[128][36];
    __shared__ float Bs[64][36];
    __shared__ int   ls[128];

    int e   = blockIdx.z;
    int cnt = g_cnt[e];
    int m0  = blockIdx.y * 128;
    if (m0 >= cnt) return;
    int h0  = blockIdx.x * 64;
    int off = g_off[e];

    int tid = threadIdx.x, lane = tid & 31, wid = tid >> 5;
    int wm = wid >> 1, wn = wid & 1;

    if (tid < 128) {
        int gm = m0 + tid;
        ls[tid] = (gm < cnt) ? g_list[e * T_TOK + gm] : 0;
    }
    __syncthreads();

    float acc[2][4][4];
#pragma unroll
    for (int i = 0; i < 2; i++)
#pragma unroll
        for (int j = 0; j < 4; j++)
#pragma unroll
            for (int k = 0; k < 4; k++) acc[i][j][k] = 0.f;

    const float* w2e  = w2 + ((size_t)e * H_DIM + h0) * F_DIM;
    const float* arow = g_act + (size_t)(off + m0) * F_DIM;

    for (int k0 = 0; k0 < F_DIM; k0 += 32) {
        // stage A (contiguous rows of act)
#pragma unroll
        for (int t = 0; t < 4; t++) {
            int idx = tid + t * 256;
            int r = idx >> 3, c4 = (idx & 7) * 4;
            float4 v = *reinterpret_cast<const float4*>(arow + (size_t)r * F_DIM + k0 + c4);
            *reinterpret_cast<float4*>(&As[r][c4]) =
                make_float4(to_tf32(v.x), to_tf32(v.y), to_tf32(v.z), to_tf32(v.w));
        }
        // stage B
#pragma unroll
        for (int t = 0; t < 2; t++) {
            int idx = tid + t * 256;
            int r = idx >> 3, c4 = (idx & 7) * 4;
            float4 v = *reinterpret_cast<const float4*>(w2e + (size_t)r * F_DIM + k0 + c4);
            *reinterpret_cast<float4*>(&Bs[r][c4]) =
                make_float4(to_tf32(v.x), to_tf32(v.y), to_tf32(v.z), to_tf32(v.w));
        }
        __syncthreads();
#pragma unroll
        for (int ks = 0; ks < 4; ks++) {
            int kk = ks * 8;
            float a[2][4];
#pragma unroll
            for (int mt = 0; mt < 2; mt++) {
                int r = wm * 32 + mt * 16 + (lane >> 2);
                int c = kk + (lane & 3);
                a[mt][0] = As[r][c];     a[mt][1] = As[r + 8][c];
                a[mt][2] = As[r][c + 4]; a[mt][3] = As[r + 8][c + 4];
            }
#pragma unroll
            for (int nt = 0; nt < 4; nt++) {
                int col = wn * 32 + nt * 8 + (lane >> 2);
                int c = kk + (lane & 3);
                float b[2] = { Bs[col][c], Bs[col][c + 4] };
#pragma unroll
                for (int mt = 0; mt < 2; mt++) mma_tf32(acc[mt][nt], a[mt], b);
            }
        }
        __syncthreads();
    }

    // epilogue: atomicAdd into out (exactly 2 contributions per element; fp32 add is commutative)
#pragma unroll
    for (int mt = 0; mt < 2; mt++) {
        int rbase = wm * 32 + mt * 16 + (lane >> 2);
#pragma unroll
        for (int half = 0; half < 2; half++) {
            int m = rbase + half * 8;
            if (m0 + m >= cnt) continue;
            int token = ls[m];
#pragma unroll
            for (int nt = 0; nt < 4; nt++) {
                int h = h0 + wn * 32 + nt * 8 + (lane & 3) * 2;
                atomicAdd(&out[(size_t)token * H_DIM + h],     acc[mt][nt][half * 2 + 0]);
                atomicAdd(&out[(size_t)token * H_DIM + h + 1], acc[mt][nt][half * 2 + 1]);
            }
        }
    }
}

// ---------------------------------------------------------------- launch
extern "C" void kernel_launch(void* const* d_in, const int* in_sizes, int n_in,
                              void* d_out, int out_size) {
    const float* x  = (const float*)d_in[0];   // [T, H]
    const float* gw = (const float*)d_in[1];   // [E, H]
    const float* w1 = (const float*)d_in[2];   // [E, F, H]
    const float* w2 = (const float*)d_in[3];   // [E, H, F]
    const float* w3 = (const float*)d_in[4];   // [E, F, H]
    float* out = (float*)d_out;                // [T, H]

    zero_kernel<<<2048, 256>>>((float4*)out);                 // 2048*256*4 = 2M floats
    router_kernel<<<T_TOK / 8, 256>>>(x, gw);                 // warp per token
    build_kernel<<<1, 256>>>();
    dim3 g1(F_DIM / 64, T_TOK / 128, E_NUM);                  // (64, 16, 8)
    mlp1_kernel<<<g1, 256>>>(x, w1, w3);
    dim3 g2(H_DIM / 64, T_TOK / 128, E_NUM);                  // (16, 16, 8)
    mlp2_kernel<<<g2, 256>>>(w2, out);
}

// round 2
// speedup vs baseline: 1.5231x; 1.5231x over previous
#include <cuda_runtime.h>
#include <math.h>
#include <stdint.h>

#define T_TOK 2048
#define H_DIM 1024
#define F_DIM 4096
#define E_NUM 8
#define STAGES 4

// Scratch (static device globals: allocation-free per harness rules)
__device__ float g_act[(4096 + 256) * F_DIM];
__device__ int   g_list[E_NUM * T_TOK];
__device__ float g_wgt [E_NUM * T_TOK];
__device__ int   g_cnt[E_NUM];
__device__ int   g_off[E_NUM];
__device__ int   g_tidx[T_TOK * 2];
__device__ float g_tw  [T_TOK * 2];

__device__ __forceinline__ float to_tf32(float x) {
    unsigned u;
    asm("cvt.rna.tf32.f32 %0, %1;" : "=r"(u) : "f"(x));
    return __uint_as_float(u);
}

__device__ __forceinline__ void mma_tf32(float* c, const float* a, const float* b) {
    const unsigned* A = reinterpret_cast<const unsigned*>(a);
    const unsigned* B = reinterpret_cast<const unsigned*>(b);
    asm volatile(
        "mma.sync.aligned.m16n8k8.row.col.f32.tf32.tf32.f32 "
        "{%0,%1,%2,%3}, {%4,%5,%6,%7}, {%8,%9}, {%0,%1,%2,%3};\n"
        : "+f"(c[0]), "+f"(c[1]), "+f"(c[2]), "+f"(c[3])
        : "r"(A[0]), "r"(A[1]), "r"(A[2]), "r"(A[3]), "r"(B[0]), "r"(B[1]));
}

__device__ __forceinline__ void cp_async16(void* smem_dst, const void* gmem_src) {
    unsigned s = (unsigned)__cvta_generic_to_shared(smem_dst);
    asm volatile("cp.async.cg.shared.global [%0], [%1], 16;\n" :: "r"(s), "l"(gmem_src));
}
#define CP_COMMIT() asm volatile("cp.async.commit_group;\n")
#define CP_WAIT(n)  asm volatile("cp.async.wait_group %0;\n" :: "n"(n))

__device__ __forceinline__ float gelu_exact(float v) {
    return 0.5f * v * (1.0f + erff(v * 0.70710678118654752440f));
}

// ---------------------------------------------------------------- zero output
__global__ void zero_kernel(float4* out) {
    out[blockIdx.x * blockDim.x + threadIdx.x] = make_float4(0.f, 0.f, 0.f, 0.f);
}

// ---------------------------------------------------------------- router
__global__ void router_kernel(const float* __restrict__ x, const float* __restrict__ gw) {
    int warp = (blockIdx.x * blockDim.x + threadIdx.x) >> 5;
    int lane = threadIdx.x & 31;
    if (warp >= T_TOK) return;
    float acc[E_NUM];
#pragma unroll
    for (int e = 0; e < E_NUM; e++) acc[e] = 0.f;
    const float* xr = x + (size_t)warp * H_DIM;
    for (int h = lane; h < H_DIM; h += 32) {
        float xv = xr[h];
#pragma unroll
        for (int e = 0; e < E_NUM; e++) acc[e] += xv * gw[e * H_DIM + h];
    }
#pragma unroll
    for (int e = 0; e < E_NUM; e++) {
#pragma unroll
        for (int o = 16; o > 0; o >>= 1) acc[e] += __shfl_xor_sync(0xffffffffu, acc[e], o);
    }
    if (lane == 0) {
        float p[E_NUM], mx = -1e30f;
#pragma unroll
        for (int e = 0; e < E_NUM; e++) {
            p[e] = 30.0f * tanhf(acc[e] * (1.0f / 30.0f));
            mx = fmaxf(mx, p[e]);
        }
        float s = 0.f;
#pragma unroll
        for (int e = 0; e < E_NUM; e++) { p[e] = expf(p[e] - mx); s += p[e]; }
        int i0 = 0;
#pragma unroll
        for (int e = 1; e < E_NUM; e++) if (p[e] > p[i0]) i0 = e;
        int i1 = (i0 == 0) ? 1 : 0;
#pragma unroll
        for (int e = 0; e < E_NUM; e++) if (e != i0 && p[e] > p[i1]) i1 = e;
        float inv = 1.0f / s;
        g_tidx[warp * 2 + 0] = i0;  g_tw[warp * 2 + 0] = p[i0] * inv;
        g_tidx[warp * 2 + 1] = i1;  g_tw[warp * 2 + 1] = p[i1] * inv;
    }
}

// ---------------------------------------------------------------- build per-expert lists
__global__ void build_kernel() {
    int e    = threadIdx.x >> 5;
    int lane = threadIdx.x & 31;
    int cnt  = 0;
    for (int base = 0; base < T_TOK; base += 32) {
        int t = base + lane;
        int i0 = g_tidx[t * 2], i1 = g_tidx[t * 2 + 1];
        bool hit = (i0 == e) || (i1 == e);
        float w = (i0 == e) ? g_tw[t * 2] : g_tw[t * 2 + 1];
        unsigned mask = __ballot_sync(0xffffffffu, hit);
        if (hit) {
            int pos = cnt + __popc(mask & ((1u << lane) - 1u));
            g_list[e * T_TOK + pos] = t;
            g_wgt [e * T_TOK + pos] = w;
        }
        cnt += __popc(mask);
    }
    if (lane == 0) g_cnt[e] = cnt;
    __syncthreads();
    if (threadIdx.x == 0) {
        int off = 0;
        for (int ee = 0; ee < E_NUM; ee++) { g_off[ee] = off; off += g_cnt[ee]; }
    }
}

// ---------------------------------------------------------------- GEMM1
// act = w * gelu(X W1^T) * (X W3^T).  M=128, N=64(x2 mats), K=32, 4-stage cp.async.
#define S1_A   4608           // 128*36 floats
#define S1_B   2304           // 64*36 floats
#define S1_TOT (S1_A + 2 * S1_B)   // 9216 floats per stage

extern __shared__ float dynsm[];

__device__ __forceinline__ void load1(float* sm, int buf, int k0,
                                      const float* __restrict__ x,
                                      const float* __restrict__ w1e,
                                      const float* __restrict__ w3e,
                                      const int* ls, int tid) {
    float* As_ = sm + buf * S1_TOT;
    float* B1_ = As_ + S1_A;
    float* B3_ = B1_ + S1_B;
#pragma unroll
    for (int t = 0; t < 4; t++) {
        int idx = tid + t * 256;
        int r = idx >> 3, c4 = (idx & 7) * 4;
        cp_async16(&As_[r * 36 + c4], x + (size_t)ls[r] * H_DIM + k0 + c4);
    }
#pragma unroll
    for (int t = 0; t < 2; t++) {
        int idx = tid + t * 256;
        int r = idx >> 3, c4 = (idx & 7) * 4;
        cp_async16(&B1_[r * 36 + c4], w1e + (size_t)r * H_DIM + k0 + c4);
        cp_async16(&B3_[r * 36 + c4], w3e + (size_t)r * H_DIM + k0 + c4);
    }
}

__global__ __launch_bounds__(256, 1) void mlp1_kernel(
        const float* __restrict__ x,
        const float* __restrict__ w1,
        const float* __restrict__ w3) {
    __shared__ int   ls[128];
    __shared__ float ws[128];

    int e   = blockIdx.z;
    int cnt = g_cnt[e];
    int m0  = blockIdx.y * 128;
    if (m0 >= cnt) return;
    int f0  = blockIdx.x * 64;
    int off = g_off[e];

    int tid = threadIdx.x, lane = tid & 31, wid = tid >> 5;
    int wm = wid >> 1, wn = wid & 1;

    if (tid < 128) {
        int gm = m0 + tid;
        ls[tid] = (gm < cnt) ? g_list[e * T_TOK + gm] : 0;
        ws[tid] = (gm < cnt) ? g_wgt [e * T_TOK + gm] : 0.f;
    }
    __syncthreads();

    float accG[2][4][4], accU[2][4][4];
#pragma unroll
    for (int i = 0; i < 2; i++)
#pragma unroll
        for (int j = 0; j < 4; j++)
#pragma unroll
            for (int k = 0; k < 4; k++) { accG[i][j][k] = 0.f; accU[i][j][k] = 0.f; }

    const float* w1e = w1 + ((size_t)e * F_DIM + f0) * H_DIM;
    const float* w3e = w3 + ((size_t)e * F_DIM + f0) * H_DIM;

    const int NT = H_DIM / 32;   // 32
#pragma unroll
    for (int s = 0; s < STAGES - 1; s++) {
        load1(dynsm, s, s * 32, x, w1e, w3e, ls, tid);
        CP_COMMIT();
    }

    for (int kt = 0; kt < NT; kt++) {
        CP_WAIT(STAGES - 2);
        __syncthreads();
        int nxt = kt + STAGES - 1;
        if (nxt < NT) load1(dynsm, nxt & (STAGES - 1), nxt * 32, x, w1e, w3e, ls, tid);
        CP_COMMIT();

        float* As_ = dynsm + (kt & (STAGES - 1)) * S1_TOT;
        float* B1_ = As_ + S1_A;
        float* B3_ = B1_ + S1_B;
#pragma unroll
        for (int ks = 0; ks < 4; ks++) {
            int kk = ks * 8;
            float a[2][4];
#pragma unroll
            for (int mt = 0; mt < 2; mt++) {
                int r = wm * 32 + mt * 16 + (lane >> 2);
                int c = kk + (lane & 3);
                a[mt][0] = to_tf32(As_[r * 36 + c]);
                a[mt][1] = to_tf32(As_[(r + 8) * 36 + c]);
                a[mt][2] = to_tf32(As_[r * 36 + c + 4]);
                a[mt][3] = to_tf32(As_[(r + 8) * 36 + c + 4]);
            }
#pragma unroll
            for (int nt = 0; nt < 4; nt++) {
                int col = wn * 32 + nt * 8 + (lane >> 2);
                int c = kk + (lane & 3);
                float b1[2] = { to_tf32(B1_[col * 36 + c]), to_tf32(B1_[col * 36 + c + 4]) };
                float b3[2] = { to_tf32(B3_[col * 36 + c]), to_tf32(B3_[col * 36 + c + 4]) };
#pragma unroll
                for (int mt = 0; mt < 2; mt++) {
                    mma_tf32(accG[mt][nt], a[mt], b1);
                    mma_tf32(accU[mt][nt], a[mt], b3);
                }
            }
        }
    }

    // epilogue: act = weight * gelu(g) * u
#pragma unroll
    for (int mt = 0; mt < 2; mt++) {
        int rbase = wm * 32 + mt * 16 + (lane >> 2);
#pragma unroll
        for (int half = 0; half < 2; half++) {
            int m = rbase + half * 8;
            if (m0 + m >= cnt) continue;
            float wgt = ws[m];
            size_t rowoff = (size_t)(off + m0 + m) * F_DIM;
#pragma unroll
            for (int nt = 0; nt < 4; nt++) {
                int col = f0 + wn * 32 + nt * 8 + (lane & 3) * 2;
                float gg0 = accG[mt][nt][half * 2 + 0];
                float gg1 = accG[mt][nt][half * 2 + 1];
                float uu0 = accU[mt][nt][half * 2 + 0];
                float uu1 = accU[mt][nt][half * 2 + 1];
                float2 o;
                o.x = wgt * uu0 * gelu_exact(gg0);
                o.y = wgt * uu1 * gelu_exact(gg1);
                *reinterpret_cast<float2*>(&g_act[rowoff + col]) = o;
            }
        }
    }
}

// ---------------------------------------------------------------- GEMM2: out += act @ W2^T
#define S2_A   4608
#define S2_B   2304
#define S2_TOT (S2_A + S2_B)   // 6912 floats per stage

__device__ __forceinline__ void load2(float* sm, int buf, int k0,
                                      const float* __restrict__ arow,
                                      const float* __restrict__ w2e, int tid) {
    float* As_ = sm + buf * S2_TOT;
    float* Bs_ = As_ + S2_A;
#pragma unroll
    for (int t = 0; t < 4; t++) {
        int idx = tid + t * 256;
        int r = idx >> 3, c4 = (idx & 7) * 4;
        cp_async16(&As_[r * 36 + c4], arow + (size_t)r * F_DIM + k0 + c4);
    }
#pragma unroll
    for (int t = 0; t < 2; t++) {
        int idx = tid + t * 256;
        int r = idx >> 3, c4 = (idx & 7) * 4;
        cp_async16(&Bs_[r * 36 + c4], w2e + (size_t)r * F_DIM + k0 + c4);
    }
}

__global__ __launch_bounds__(256, 1) void mlp2_kernel(
        const float* __restrict__ w2, float* __restrict__ out) {
    __shared__ int ls[128];

    int e   = blockIdx.z;
    int cnt = g_cnt[e];
    int m0  = blockIdx.y * 128;
    if (m0 >= cnt) return;
    int h0  = blockIdx.x * 64;
    int off = g_off[e];

    int tid = threadIdx.x, lane = tid & 31, wid = tid >> 5;
    int wm = wid >> 1, wn = wid & 1;

    if (tid < 128) {
        int gm = m0 + tid;
        ls[tid] = (gm < cnt) ? g_list[e * T_TOK + gm] : 0;
    }
    __syncthreads();

    float acc[2][4][4];
#pragma unroll
    for (int i = 0; i < 2; i++)
#pragma unroll
        for (int j = 0; j < 4; j++)
#pragma unroll
            for (int k = 0; k < 4; k++) acc[i][j][k] = 0.f;

    const float* w2e  = w2 + ((size_t)e * H_DIM + h0) * F_DIM;
    const float* arow = g_act + (size_t)(off + m0) * F_DIM;

    const int NT = F_DIM / 32;   // 128
#pragma unroll
    for (int s = 0; s < STAGES - 1; s++) {
        load2(dynsm, s, s * 32, arow, w2e, tid);
        CP_COMMIT();
    }

    for (int kt = 0; kt < NT; kt++) {
        CP_WAIT(STAGES - 2);
        __syncthreads();
        int nxt = kt + STAGES - 1;
        if (nxt < NT) load2(dynsm, nxt & (STAGES - 1), nxt * 32, arow, w2e, tid);
        CP_COMMIT();

        float* As_ = dynsm + (kt & (STAGES - 1)) * S2_TOT;
        float* Bs_ = As_ + S2_A;
#pragma unroll
        for (int ks = 0; ks < 4; ks++) {
            int kk = ks * 8;
            float a[2][4];
#pragma unroll
            for (int mt = 0; mt < 2; mt++) {
                int r = wm * 32 + mt * 16 + (lane >> 2);
                int c = kk + (lane & 3);
                a[mt][0] = to_tf32(As_[r * 36 + c]);
                a[mt][1] = to_tf32(As_[(r + 8) * 36 + c]);
                a[mt][2] = to_tf32(As_[r * 36 + c + 4]);
                a[mt][3] = to_tf32(As_[(r + 8) * 36 + c + 4]);
            }
#pragma unroll
            for (int nt = 0; nt < 4; nt++) {
                int col = wn * 32 + nt * 8 + (lane >> 2);
                int c = kk + (lane & 3);
                float b[2] = { to_tf32(Bs_[col * 36 + c]), to_tf32(Bs_[col * 36 + c + 4]) };
#pragma unroll
                for (int mt = 0; mt < 2; mt++) mma_tf32(acc[mt][nt], a[mt], b);
            }
        }
    }

    // epilogue: atomicAdd into out (exactly 2 commutative fp32 adds per element)
#pragma unroll
    for (int mt = 0; mt < 2; mt++) {
        int rbase = wm * 32 + mt * 16 + (lane >> 2);
#pragma unroll
        for (int half = 0; half < 2; half++) {
            int m = rbase + half * 8;
            if (m0 + m >= cnt) continue;
            int token = ls[m];
#pragma unroll
            for (int nt = 0; nt < 4; nt++) {
                int h = h0 + wn * 32 + nt * 8 + (lane & 3) * 2;
                atomicAdd(&out[(size_t)token * H_DIM + h],     acc[mt][nt][half * 2 + 0]);
                atomicAdd(&out[(size_t)token * H_DIM + h + 1], acc[mt][nt][half * 2 + 1]);
            }
        }
    }
}

// ---------------------------------------------------------------- launch
extern "C" void kernel_launch(void* const* d_in, const int* in_sizes, int n_in,
                              void* d_out, int out_size) {
    const float* x  = (const float*)d_in[0];   // [T, H]
    const float* gw = (const float*)d_in[1];   // [E, H]
    const float* w1 = (const float*)d_in[2];   // [E, F, H]
    const float* w2 = (const float*)d_in[3];   // [E, H, F]
    const float* w3 = (const float*)d_in[4];   // [E, F, H]
    float* out = (float*)d_out;                // [T, H]

    const int smem1 = STAGES * S1_TOT * 4;   // 147456 B
    const int smem2 = STAGES * S2_TOT * 4;   // 110592 B
    cudaFuncSetAttribute(mlp1_kernel, cudaFuncAttributeMaxDynamicSharedMemorySize, smem1);
    cudaFuncSetAttribute(mlp2_kernel, cudaFuncAttributeMaxDynamicSharedMemorySize, smem2);

    zero_kernel<<<2048, 256>>>((float4*)out);
    router_kernel<<<T_TOK / 8, 256>>>(x, gw);
    build_kernel<<<1, 256>>>();
    dim3 g1(F_DIM / 64, T_TOK / 128, E_NUM);
    mlp1_kernel<<<g1, 256, smem1>>>(x, w1, w3);
    dim3 g2(H_DIM / 64, T_TOK / 128, E_NUM);
    mlp2_kernel<<<g2, 256, smem2>>>(w2, out);
}

// round 3
// speedup vs baseline: 1.7087x; 1.1219x over previous
#include <cuda_runtime.h>
#include <math.h>
#include <stdint.h>

#define T_TOK 2048
#define H_DIM 1024
#define F_DIM 4096
#define E_NUM 8
#define STAGES 3

// Scratch (static device globals: allocation-free per harness rules)
__device__ float g_act[(4096 + 256) * F_DIM];
__device__ int   g_list[E_NUM * T_TOK];
__device__ float g_wgt [E_NUM * T_TOK];
__device__ int   g_cnt[E_NUM];
__device__ int   g_off[E_NUM];
__device__ int   g_tidx[T_TOK * 2];
__device__ float g_tw  [T_TOK * 2];

__device__ __forceinline__ float to_tf32(float x) {
    unsigned u;
    asm("cvt.rna.tf32.f32 %0, %1;" : "=r"(u) : "f"(x));
    return __uint_as_float(u);
}

__device__ __forceinline__ void mma_tf32(float* c, const float* a, const float* b) {
    const unsigned* A = reinterpret_cast<const unsigned*>(a);
    const unsigned* B = reinterpret_cast<const unsigned*>(b);
    asm volatile(
        "mma.sync.aligned.m16n8k8.row.col.f32.tf32.tf32.f32 "
        "{%0,%1,%2,%3}, {%4,%5,%6,%7}, {%8,%9}, {%0,%1,%2,%3};\n"
        : "+f"(c[0]), "+f"(c[1]), "+f"(c[2]), "+f"(c[3])
        : "r"(A[0]), "r"(A[1]), "r"(A[2]), "r"(A[3]), "r"(B[0]), "r"(B[1]));
}

__device__ __forceinline__ void cp_async16(void* smem_dst, const void* gmem_src) {
    unsigned s = (unsigned)__cvta_generic_to_shared(smem_dst);
    asm volatile("cp.async.cg.shared.global [%0], [%1], 16;\n" :: "r"(s), "l"(gmem_src));
}
#define CP_COMMIT() asm volatile("cp.async.commit_group;\n")
#define CP_WAIT(n)  asm volatile("cp.async.wait_group %0;\n" :: "n"(n))

__device__ __forceinline__ float gelu_exact(float v) {
    return 0.5f * v * (1.0f + erff(v * 0.70710678118654752440f));
}

// ---------------------------------------------------------------- zero output
__global__ void zero_kernel(float4* out) {
    out[blockIdx.x * blockDim.x + threadIdx.x] = make_float4(0.f, 0.f, 0.f, 0.f);
}

// ---------------------------------------------------------------- router
__global__ void router_kernel(const float* __restrict__ x, const float* __restrict__ gw) {
    int warp = (blockIdx.x * blockDim.x + threadIdx.x) >> 5;
    int lane = threadIdx.x & 31;
    if (warp >= T_TOK) return;
    float acc[E_NUM];
#pragma unroll
    for (int e = 0; e < E_NUM; e++) acc[e] = 0.f;
    const float* xr = x + (size_t)warp * H_DIM;
    for (int h = lane; h < H_DIM; h += 32) {
        float xv = xr[h];
#pragma unroll
        for (int e = 0; e < E_NUM; e++) acc[e] += xv * gw[e * H_DIM + h];
    }
#pragma unroll
    for (int e = 0; e < E_NUM; e++) {
#pragma unroll
        for (int o = 16; o > 0; o >>= 1) acc[e] += __shfl_xor_sync(0xffffffffu, acc[e], o);
    }
    if (lane == 0) {
        float p[E_NUM], mx = -1e30f;
#pragma unroll
        for (int e = 0; e < E_NUM; e++) {
            p[e] = 30.0f * tanhf(acc[e] * (1.0f / 30.0f));
            mx = fmaxf(mx, p[e]);
        }
        float s = 0.f;
#pragma unroll
        for (int e = 0; e < E_NUM; e++) { p[e] = expf(p[e] - mx); s += p[e]; }
        int i0 = 0;
#pragma unroll
        for (int e = 1; e < E_NUM; e++) if (p[e] > p[i0]) i0 = e;
        int i1 = (i0 == 0) ? 1 : 0;
#pragma unroll
        for (int e = 0; e < E_NUM; e++) if (e != i0 && p[e] > p[i1]) i1 = e;
        float inv = 1.0f / s;
        g_tidx[warp * 2 + 0] = i0;  g_tw[warp * 2 + 0] = p[i0] * inv;
        g_tidx[warp * 2 + 1] = i1;  g_tw[warp * 2 + 1] = p[i1] * inv;
    }
}

// ---------------------------------------------------------------- build per-expert lists
__global__ void build_kernel() {
    int e    = threadIdx.x >> 5;
    int lane = threadIdx.x & 31;
    int cnt  = 0;
    for (int base = 0; base < T_TOK; base += 32) {
        int t = base + lane;
        int i0 = g_tidx[t * 2], i1 = g_tidx[t * 2 + 1];
        bool hit = (i0 == e) || (i1 == e);
        float w = (i0 == e) ? g_tw[t * 2] : g_tw[t * 2 + 1];
        unsigned mask = __ballot_sync(0xffffffffu, hit);
        if (hit) {
            int pos = cnt + __popc(mask & ((1u << lane) - 1u));
            g_list[e * T_TOK + pos] = t;
            g_wgt [e * T_TOK + pos] = w;
        }
        cnt += __popc(mask);
    }
    if (lane == 0) g_cnt[e] = cnt;
    __syncthreads();
    if (threadIdx.x == 0) {
        int off = 0;
        for (int ee = 0; ee < E_NUM; ee++) { g_off[ee] = off; off += g_cnt[ee]; }
    }
}

// ---------------------------------------------------------------- GEMM1
// act = w * gelu(X W1^T) * (X W3^T).  M=128, N=64(x2 mats), K=32, 3-stage cp.async,
// 2 CTAs/SM for latency hiding.
#define S1_A   4608           // 128*36 floats
#define S1_B   2304           // 64*36 floats
#define S1_TOT (S1_A + 2 * S1_B)   // 9216 floats per stage

extern __shared__ float dynsm[];

__device__ __forceinline__ void load1(float* sm, int buf, int k0,
                                      const float* __restrict__ x,
                                      const float* __restrict__ w1e,
                                      const float* __restrict__ w3e,
                                      const int* ls, int tid) {
    float* As_ = sm + buf * S1_TOT;
    float* B1_ = As_ + S1_A;
    float* B3_ = B1_ + S1_B;
#pragma unroll
    for (int t = 0; t < 4; t++) {
        int idx = tid + t * 256;
        int r = idx >> 3, c4 = (idx & 7) * 4;
        cp_async16(&As_[r * 36 + c4], x + (size_t)ls[r] * H_DIM + k0 + c4);
    }
#pragma unroll
    for (int t = 0; t < 2; t++) {
        int idx = tid + t * 256;
        int r = idx >> 3, c4 = (idx & 7) * 4;
        cp_async16(&B1_[r * 36 + c4], w1e + (size_t)r * H_DIM + k0 + c4);
        cp_async16(&B3_[r * 36 + c4], w3e + (size_t)r * H_DIM + k0 + c4);
    }
}

__global__ __launch_bounds__(256, 2) void mlp1_kernel(
        const float* __restrict__ x,
        const float* __restrict__ w1,
        const float* __restrict__ w3) {
    __shared__ int   ls[128];
    __shared__ float ws[128];

    int e   = blockIdx.z;
    int cnt = g_cnt[e];
    int m0  = blockIdx.y * 128;
    if (m0 >= cnt) return;
    int f0  = blockIdx.x * 64;
    int off = g_off[e];

    int tid = threadIdx.x, lane = tid & 31, wid = tid >> 5;
    int wm = wid >> 1, wn = wid & 1;

    if (tid < 128) {
        int gm = m0 + tid;
        ls[tid] = (gm < cnt) ? g_list[e * T_TOK + gm] : 0;
        ws[tid] = (gm < cnt) ? g_wgt [e * T_TOK + gm] : 0.f;
    }
    __syncthreads();

    float accG[2][4][4], accU[2][4][4];
#pragma unroll
    for (int i = 0; i < 2; i++)
#pragma unroll
        for (int j = 0; j < 4; j++)
#pragma unroll
            for (int k = 0; k < 4; k++) { accG[i][j][k] = 0.f; accU[i][j][k] = 0.f; }

    const float* w1e = w1 + ((size_t)e * F_DIM + f0) * H_DIM;
    const float* w3e = w3 + ((size_t)e * F_DIM + f0) * H_DIM;

    const int NT = H_DIM / 32;   // 32
#pragma unroll
    for (int s = 0; s < STAGES - 1; s++) {
        load1(dynsm, s, s * 32, x, w1e, w3e, ls, tid);
        CP_COMMIT();
    }

    int cbuf = 0, pbuf = STAGES - 1;
    for (int kt = 0; kt < NT; kt++) {
        CP_WAIT(STAGES - 2);
        __syncthreads();
        int nxt = kt + STAGES - 1;
        if (nxt < NT) load1(dynsm, pbuf, nxt * 32, x, w1e, w3e, ls, tid);
        CP_COMMIT();
        if (++pbuf == STAGES) pbuf = 0;

        float* As_ = dynsm + cbuf * S1_TOT;
        float* B1_ = As_ + S1_A;
        float* B3_ = B1_ + S1_B;
        if (++cbuf == STAGES) cbuf = 0;
#pragma unroll
        for (int ks = 0; ks < 4; ks++) {
            int kk = ks * 8;
            float a[2][4];
#pragma unroll
            for (int mt = 0; mt < 2; mt++) {
                int r = wm * 32 + mt * 16 + (lane >> 2);
                int c = kk + (lane & 3);
                a[mt][0] = to_tf32(As_[r * 36 + c]);
                a[mt][1] = to_tf32(As_[(r + 8) * 36 + c]);
                a[mt][2] = to_tf32(As_[r * 36 + c + 4]);
                a[mt][3] = to_tf32(As_[(r + 8) * 36 + c + 4]);
            }
#pragma unroll
            for (int nt = 0; nt < 4; nt++) {
                int col = wn * 32 + nt * 8 + (lane >> 2);
                int c = kk + (lane & 3);
                float b1[2] = { to_tf32(B1_[col * 36 + c]), to_tf32(B1_[col * 36 + c + 4]) };
                float b3[2] = { to_tf32(B3_[col * 36 + c]), to_tf32(B3_[col * 36 + c + 4]) };
#pragma unroll
                for (int mt = 0; mt < 2; mt++) {
                    mma_tf32(accG[mt][nt], a[mt], b1);
                    mma_tf32(accU[mt][nt], a[mt], b3);
                }
            }
        }
    }

    // epilogue: act = weight * gelu(g) * u
#pragma unroll
    for (int mt = 0; mt < 2; mt++) {
        int rbase = wm * 32 + mt * 16 + (lane >> 2);
#pragma unroll
        for (int half = 0; half < 2; half++) {
            int m = rbase + half * 8;
            if (m0 + m >= cnt) continue;
            float wgt = ws[m];
            size_t rowoff = (size_t)(off + m0 + m) * F_DIM;
#pragma unroll
            for (int nt = 0; nt < 4; nt++) {
                int col = f0 + wn * 32 + nt * 8 + (lane & 3) * 2;
                float gg0 = accG[mt][nt][half * 2 + 0];
                float gg1 = accG[mt][nt][half * 2 + 1];
                float uu0 = accU[mt][nt][half * 2 + 0];
                float uu1 = accU[mt][nt][half * 2 + 1];
                float2 o;
                o.x = wgt * uu0 * gelu_exact(gg0);
                o.y = wgt * uu1 * gelu_exact(gg1);
                *reinterpret_cast<float2*>(&g_act[rowoff + col]) = o;
            }
        }
    }
}

// ---------------------------------------------------------------- GEMM2: out += act @ W2^T
#define S2_A   4608
#define S2_B   2304
#define S2_TOT (S2_A + S2_B)   // 6912 floats per stage

__device__ __forceinline__ void load2(float* sm, int buf, int k0,
                                      const float* __restrict__ arow,
                                      const float* __restrict__ w2e, int tid) {
    float* As_ = sm + buf * S2_TOT;
    float* Bs_ = As_ + S2_A;
#pragma unroll
    for (int t = 0; t < 4; t++) {
        int idx = tid + t * 256;
        int r = idx >> 3, c4 = (idx & 7) * 4;
        cp_async16(&As_[r * 36 + c4], arow + (size_t)r * F_DIM + k0 + c4);
    }
#pragma unroll
    for (int t = 0; t < 2; t++) {
        int idx = tid + t * 256;
        int r = idx >> 3, c4 = (idx & 7) * 4;
        cp_async16(&Bs_[r * 36 + c4], w2e + (size_t)r * F_DIM + k0 + c4);
    }
}

__global__ __launch_bounds__(256, 2) void mlp2_kernel(
        const float* __restrict__ w2, float* __restrict__ out) {
    __shared__ int ls[128];

    int e   = blockIdx.z;
    int cnt = g_cnt[e];
    int m0  = blockIdx.y * 128;
    if (m0 >= cnt) return;
    int h0  = blockIdx.x * 64;
    int off = g_off[e];

    int tid = threadIdx.x, lane = tid & 31, wid = tid >> 5;
    int wm = wid >> 1, wn = wid & 1;

    if (tid < 128) {
        int gm = m0 + tid;
        ls[tid] = (gm < cnt) ? g_list[e * T_TOK + gm] : 0;
    }
    __syncthreads();

    float acc[2][4][4];
#pragma unroll
    for (int i = 0; i < 2; i++)
#pragma unroll
        for (int j = 0; j < 4; j++)
#pragma unroll
            for (int k = 0; k < 4; k++) acc[i][j][k] = 0.f;

    const float* w2e  = w2 + ((size_t)e * H_DIM + h0) * F_DIM;
    const float* arow = g_act + (size_t)(off + m0) * F_DIM;

    const int NT = F_DIM / 32;   // 128
#pragma unroll
    for (int s = 0; s < STAGES - 1; s++) {
        load2(dynsm, s, s * 32, arow, w2e, tid);
        CP_COMMIT();
    }

    int cbuf = 0, pbuf = STAGES - 1;
    for (int kt = 0; kt < NT; kt++) {
        CP_WAIT(STAGES - 2);
        __syncthreads();
        int nxt = kt + STAGES - 1;
        if (nxt < NT) load2(dynsm, pbuf, nxt * 32, arow, w2e, tid);
        CP_COMMIT();
        if (++pbuf == STAGES) pbuf = 0;

        float* As_ = dynsm + cbuf * S2_TOT;
        float* Bs_ = As_ + S2_A;
        if (++cbuf == STAGES) cbuf = 0;
#pragma unroll
        for (int ks = 0; ks < 4; ks++) {
            int kk = ks * 8;
            float a[2][4];
#pragma unroll
            for (int mt = 0; mt < 2; mt++) {
                int r = wm * 32 + mt * 16 + (lane >> 2);
                int c = kk + (lane & 3);
                a[mt][0] = to_tf32(As_[r * 36 + c]);
                a[mt][1] = to_tf32(As_[(r + 8) * 36 + c]);
                a[mt][2] = to_tf32(As_[r * 36 + c + 4]);
                a[mt][3] = to_tf32(As_[(r + 8) * 36 + c + 4]);
            }
#pragma unroll
            for (int nt = 0; nt < 4; nt++) {
                int col = wn * 32 + nt * 8 + (lane >> 2);
                int c = kk + (lane & 3);
                float b[2] = { to_tf32(Bs_[col * 36 + c]), to_tf32(Bs_[col * 36 + c + 4]) };
#pragma unroll
                for (int mt = 0; mt < 2; mt++) mma_tf32(acc[mt][nt], a[mt], b);
            }
        }
    }

    // epilogue: atomicAdd into out (exactly 2 commutative fp32 adds per element)
#pragma unroll
    for (int mt = 0; mt < 2; mt++) {
        int rbase = wm * 32 + mt * 16 + (lane >> 2);
#pragma unroll
        for (int half = 0; half < 2; half++) {
            int m = rbase + half * 8;
            if (m0 + m >= cnt) continue;
            int token = ls[m];
#pragma unroll
            for (int nt = 0; nt < 4; nt++) {
                int h = h0 + wn * 32 + nt * 8 + (lane & 3) * 2;
                atomicAdd(&out[(size_t)token * H_DIM + h],     acc[mt][nt][half * 2 + 0]);
                atomicAdd(&out[(size_t)token * H_DIM + h + 1], acc[mt][nt][half * 2 + 1]);
            }
        }
    }
}

// ---------------------------------------------------------------- launch
extern "C" void kernel_launch(void* const* d_in, const int* in_sizes, int n_in,
                              void* d_out, int out_size) {
    const float* x  = (const float*)d_in[0];   // [T, H]
    const float* gw = (const float*)d_in[1];   // [E, H]
    const float* w1 = (const float*)d_in[2];   // [E, F, H]
    const float* w2 = (const float*)d_in[3];   // [E, H, F]
    const float* w3 = (const float*)d_in[4];   // [E, F, H]
    float* out = (float*)d_out;                // [T, H]

    const int smem1 = STAGES * S1_TOT * 4;   // 110592 B
    const int smem2 = STAGES * S2_TOT * 4;   // 82944 B
    cudaFuncSetAttribute(mlp1_kernel, cudaFuncAttributeMaxDynamicSharedMemorySize, smem1);
    cudaFuncSetAttribute(mlp2_kernel, cudaFuncAttributeMaxDynamicSharedMemorySize, smem2);

    zero_kernel<<<2048, 256>>>((float4*)out);
    router_kernel<<<T_TOK / 8, 256>>>(x, gw);
    build_kernel<<<1, 256>>>();
    dim3 g1(F_DIM / 64, T_TOK / 128, E_NUM);
    mlp1_kernel<<<g1, 256, smem1>>>(x, w1, w3);
    dim3 g2(H_DIM / 64, T_TOK / 128, E_NUM);
    mlp2_kernel<<<g2, 256, smem2>>>(w2, out);
}